// round 15
// baseline (speedup 1.0000x reference)
#include <cuda_runtime.h>
#include <math.h>

#define H 512
#define W 512
#define BATCH 16
#define NPIX (H*W)
#define CA 0.955f
#define CB 1.3693f
#define CINF 1e6f
#define BIG 1e30f
#define NG 32
#define RR 16
#define LBLK 256
#define BPI 32
#define NLB (BATCH*BPI)

#define SD  ((float)((double)CB-(double)CA))
#define S16 ((float)(16.0*((double)CB-(double)CA)))
#define C16A ((float)(16.0*(double)CA))

__device__ float    g_dist[BATCH*NPIX];
__device__ int      g_mxi[BATCH];
__device__ int      g_flags[BATCH];
__device__ float    g_part[NLB*5];
__device__ unsigned g_seed[BATCH*H*16];
__device__ float    g_L[BATCH*NG*W];

__device__ __forceinline__ void ld16(const float* b, float* a) {
    float4 x0=*(const float4*)(b+0), x1=*(const float4*)(b+4);
    float4 x2=*(const float4*)(b+8), x3=*(const float4*)(b+12);
    a[0]=x0.x;a[1]=x0.y;a[2]=x0.z;a[3]=x0.w; a[4]=x1.x;a[5]=x1.y;a[6]=x1.z;a[7]=x1.w;
    a[8]=x2.x;a[9]=x2.y;a[10]=x2.z;a[11]=x2.w; a[12]=x3.x;a[13]=x3.y;a[14]=x3.z;a[15]=x3.w;
}
__device__ __forceinline__ void st16(float* b, const float* a) {
    *(float4*)(b+0)=make_float4(a[0],a[1],a[2],a[3]);
    *(float4*)(b+4)=make_float4(a[4],a[5],a[6],a[7]);
    *(float4*)(b+8)=make_float4(a[8],a[9],a[10],a[11]);
    *(float4*)(b+12)=make_float4(a[12],a[13],a[14],a[15]);
}
__device__ __forceinline__ float scan_up(float x, int t) {
    const unsigned FM=0xffffffffu; float o;
    o=__shfl_up_sync(FM,x,1);  if(t>=1)  x=fminf(x,o);
    o=__shfl_up_sync(FM,x,2);  if(t>=2)  x=fminf(x,o);
    o=__shfl_up_sync(FM,x,4);  if(t>=4)  x=fminf(x,o);
    o=__shfl_up_sync(FM,x,8);  if(t>=8)  x=fminf(x,o);
    o=__shfl_up_sync(FM,x,16); if(t>=16) x=fminf(x,o);
    return x;
}
__device__ __forceinline__ float scan_dn(float x, int t) {
    const unsigned FM=0xffffffffu; float o;
    o=__shfl_down_sync(FM,x,1);  if(t<=30) x=fminf(x,o);
    o=__shfl_down_sync(FM,x,2);  if(t<=29) x=fminf(x,o);
    o=__shfl_down_sync(FM,x,4);  if(t<=27) x=fminf(x,o);
    o=__shfl_down_sync(FM,x,8);  if(t<=23) x=fminf(x,o);
    o=__shfl_down_sync(FM,x,16); if(t<=15) x=fminf(x,o);
    return x;
}
__device__ __forceinline__ void row_step_fwd(float* p, unsigned hw, const float* aj, int t) {
    const unsigned FM=0xffffffffu;
    float pvL=__shfl_up_sync(FM,p[15],1);  if(t==0)  pvL=CINF;
    float pvR=__shfl_down_sync(FM,p[0],1); if(t==31) pvR=CINF;
    float v[16];
    #pragma unroll
    for (int c=0;c<16;c++) {
        float pl=(c==0)?pvL:p[c-1], pr=(c==15)?pvR:p[c+1];
        float dv=((hw>>c)&1u)?0.0f:CINF;
        v[c]=fminf(fminf(dv,p[c]+CA),fminf(pl,pr)+CB)-aj[c];
    }
    #pragma unroll
    for (int c=1;c<16;c++) v[c]=fminf(v[c-1],v[c]);
    float s=scan_up(v[15],t);
    float excl=__shfl_up_sync(FM,s,1); if(t==0) excl=BIG;
    #pragma unroll
    for (int c=0;c<16;c++) p[c]=aj[c]+fminf(excl,v[c]);
}
__device__ __forceinline__ void row_step_bwd(float* p, const float* drw, const float* ar, int t) {
    const unsigned FM=0xffffffffu;
    float pvL=__shfl_up_sync(FM,p[15],1);  if(t==0)  pvL=CINF;
    float pvR=__shfl_down_sync(FM,p[0],1); if(t==31) pvR=CINF;
    float v[16];
    #pragma unroll
    for (int c=0;c<16;c++) {
        float pl=(c==0)?pvL:p[c-1], pr=(c==15)?pvR:p[c+1];
        v[c]=fminf(fminf(drw[c],p[c]+CA),fminf(pl,pr)+CB)-ar[c];
    }
    #pragma unroll
    for (int c=14;c>=0;c--) v[c]=fminf(v[c],v[c+1]);
    float s=scan_dn(v[0],t);
    float excl=__shfl_down_sync(FM,s,1); if(t==31) excl=BIG;
    #pragma unroll
    for (int c=0;c<16;c++) p[c]=ar[c]+fminf(excl,v[c]);
}
__device__ __forceinline__ void age_step(float* x, int t) {
    const unsigned FM=0xffffffffu;
    float xl=__shfl_up_sync(FM,x[15],1);  if(t==0)  xl=CINF;
    float xr=__shfl_down_sync(FM,x[0],1); if(t==31) xr=CINF;
    float y[16];
    #pragma unroll
    for (int c=0;c<16;c++) {
        float l=(c==0)?xl:x[c-1], r=(c==15)?xr:x[c+1];
        y[c]=fminf(x[c]+CA,fminf(l,r)+CB);
    }
    #pragma unroll
    for (int c=0;c<16;c++) x[c]=y[c];
}
__device__ __forceinline__ void composed_step16(float* p, const float* Lc,
                                                const float* ax, int t, int dir) {
    const unsigned FM=0xffffffffu;
    float pe[48];
    #pragma unroll
    for (int k=0;k<16;k++) { float h=__shfl_up_sync(FM,p[k],1); pe[k]=(t==0)?CINF:h; }
    #pragma unroll
    for (int c=0;c<16;c++) pe[16+c]=p[c];
    #pragma unroll
    for (int k=0;k<16;k++) { float h=__shfl_down_sync(FM,p[k],1); pe[32+k]=(t==31)?CINF:h; }
    float TL[16], TR[16];
    #pragma unroll
    for (int c=0;c<16;c++) { TL[c]=pe[c]+S16; TR[c]=pe[32+c]+S16; }
    float A[48];
    #pragma unroll
    for (int i=0;i<48;i++) A[i]=pe[i];
    #pragma unroll
    for (int i=31;i>=2;i--)  A[i]=fminf(A[i],A[i-1]+SD);
    #pragma unroll
    for (int i=31;i>=4;i--)  A[i]=fminf(A[i],A[i-2]+(2.0f*SD));
    #pragma unroll
    for (int i=31;i>=8;i--)  A[i]=fminf(A[i],A[i-4]+(4.0f*SD));
    #pragma unroll
    for (int i=31;i>=16;i--) A[i]=fminf(A[i],A[i-8]+(8.0f*SD));
    #pragma unroll
    for (int i=16;i<=45;i++) pe[i]=fminf(pe[i],pe[i+1]+SD);
    #pragma unroll
    for (int i=16;i<=43;i++) pe[i]=fminf(pe[i],pe[i+2]+(2.0f*SD));
    #pragma unroll
    for (int i=16;i<=39;i++) pe[i]=fminf(pe[i],pe[i+4]+(4.0f*SD));
    #pragma unroll
    for (int i=16;i<=31;i++) pe[i]=fminf(pe[i],pe[i+8]+(8.0f*SD));
    float v[16];
    #pragma unroll
    for (int c=0;c<16;c++) {
        float b=fminf(fminf(A[16+c],TL[c]),fminf(pe[16+c],TR[c]));
        v[c]=fminf(Lc[c],b+C16A)-ax[c];
    }
    if (dir==0) {
        #pragma unroll
        for (int c=1;c<16;c++) v[c]=fminf(v[c-1],v[c]);
        float s=scan_up(v[15],t);
        float excl=__shfl_up_sync(FM,s,1); if(t==0) excl=BIG;
        #pragma unroll
        for (int c=0;c<16;c++) p[c]=ax[c]+fminf(excl,v[c]);
    } else {
        #pragma unroll
        for (int c=14;c>=0;c--) v[c]=fminf(v[c],v[c+1]);
        float s=scan_dn(v[0],t);
        float excl=__shfl_down_sync(FM,s,1); if(t==31) excl=BIG;
        #pragma unroll
        for (int c=0;c<16;c++) p[c]=ax[c]+fminf(excl,v[c]);
    }
}

__global__ __launch_bounds__(128) void seed_kernel(const int* __restrict__ target) {
    __shared__ unsigned mbits[H*18];
    __shared__ int sflag[2];
    const int img=blockIdx.x;
    const int* tg=target+img*NPIX;
    unsigned* sb=g_seed+img*H*16;
    const int tid=threadIdx.x, lane=tid&31, sl=tid&7, sg=tid>>3, col0=tid*4;
    const unsigned FM=0xffffffffu;
    if (tid<2) sflag[tid]=0;
    if (tid==0) g_mxi[img]=0;
    for (int r=tid;r<H;r+=128) { mbits[r*18+0]=0u; mbits[r*18+17]=0u; }
    __syncthreads();
    bool any1=false, any0=false;
    int4 cur=*(const int4*)(tg+col0);
    for (int r=0;r<H;r++) {
        int4 tv=cur;
        if (r<H-1) cur=*(const int4*)(tg+(r+1)*W+col0);
        unsigned nib=(unsigned)(tv.x!=0)|((unsigned)(tv.y!=0)<<1)
                    |((unsigned)(tv.z!=0)<<2)|((unsigned)(tv.w!=0)<<3);
        any1|=(nib!=0u); any0|=(nib!=15u);
        unsigned word=nib<<(4*sl);
        word|=__shfl_xor_sync(FM,word,1);
        word|=__shfl_xor_sync(FM,word,2);
        word|=__shfl_xor_sync(FM,word,4);
        if (sl==0) mbits[r*18+1+sg]=word;
    }
    if (__any_sync(FM,any1)&&lane==0) atomicOr(&sflag[0],1);
    if (__any_sync(FM,any0)&&lane==0) atomicOr(&sflag[1],1);
    __syncthreads();
    const int hasb=sflag[0]&sflag[1];
    for (int idx=tid;idx<H*16;idx+=128) {
        int r=idx>>4, w=idx&15;
        unsigned swd;
        if (hasb) {
            unsigned dil=0u, ero=0xffffffffu;
            #pragma unroll
            for (int dr=-1;dr<=1;dr++) {
                int r2=r+dr;
                if (r2<0||r2>=H) continue;
                unsigned M=mbits[r2*18+1+w], Ml=mbits[r2*18+w], Mr=mbits[r2*18+2+w];
                unsigned Mlg=(w==0)?0xffffffffu:Ml, Mrg=(w==15)?0xffffffffu:Mr;
                dil|=M|__funnelshift_l(Ml,M,1)|__funnelshift_r(M,Mr,1);
                ero&=M&__funnelshift_l(Mlg,M,1)&__funnelshift_r(M,Mrg,1);
            }
            swd=dil&~ero;
        } else swd=~mbits[r*18+1+w];
        sb[idx]=swd;
    }
    if (tid==0) g_flags[img]=sflag[0]|(sflag[1]<<1);
}

// L forward: prefetch all 16 seed words upfront
__global__ __launch_bounds__(32) void Lfwd_kernel() {
    const int g=blockIdx.x, img=blockIdx.y, t=threadIdx.x, c0=t*16;
    const int wsel=t>>1, wsh=(t&1)*16;
    unsigned sw[RR];
    #pragma unroll
    for (int k=0;k<RR;k++) sw[k]=g_seed[img*H*16+(RR*g+k)*16+wsel];
    float x[16];
    unsigned hw=(sw[0]>>wsh)&0xffffu;
    #pragma unroll
    for (int c=0;c<16;c++) x[c]=((hw>>c)&1u)?0.0f:CINF;
    for (int k=1;k<RR;k++) {
        age_step(x,t);
        unsigned h2=(sw[k]>>wsh)&0xffffu;
        #pragma unroll
        for (int c=0;c<16;c++) x[c]=fminf(x[c],((h2>>c)&1u)?0.0f:CINF);
    }
    st16(g_L+(img*NG+g)*W+c0,x);
}

__global__ __launch_bounds__(32) void serial_fwd_kernel() {
    const int img=blockIdx.x, t=threadIdx.x, c0=t*16;
    float* dd=g_dist+img*NPIX;
    const float* Lb=g_L+img*NG*W;
    float aj[16];
    #pragma unroll
    for (int c=0;c<16;c++) aj[c]=CA*(float)(c0+c);
    float p[16];
    #pragma unroll
    for (int c=0;c<16;c++) p[c]=CINF;
    float Lc[16]; ld16(Lb+c0,Lc);
    for (int g=0;g<NG;g++) {
        float Ln[16];
        if (g<NG-1) ld16(Lb+(g+1)*W+c0,Ln);
        composed_step16(p,Lc,aj,t,0);
        st16(dd+(RR*g+RR-1)*W+c0,p);
        #pragma unroll
        for (int c=0;c<16;c++) Lc[c]=Ln[c];
    }
}

// fused: fill forward rows of group g, then compute backward-L for proc group NG-1-g
__global__ __launch_bounds__(32) void fillfwd_lbwd_kernel() {
    const int g=blockIdx.x, img=blockIdx.y, t=threadIdx.x, c0=t*16;
    const int wsel=t>>1, wsh=(t&1)*16;
    float* dd=g_dist+img*NPIX;
    float aj[16];
    #pragma unroll
    for (int c=0;c<16;c++) aj[c]=CA*(float)(c0+c);
    unsigned sw[RR-1];
    #pragma unroll
    for (int k=0;k<RR-1;k++) sw[k]=g_seed[img*H*16+(RR*g+k)*16+wsel];
    float p[16];
    if (g==0) {
        #pragma unroll
        for (int c=0;c<16;c++) p[c]=CINF;
    } else ld16(dd+(RR*g-1)*W+c0,p);
    for (int k=0;k<RR-1;k++) {
        row_step_fwd(p,(sw[k]>>wsh)&0xffffu,aj,t);
        st16(dd+(RR*g+k)*W+c0,p);
    }
    // backward-L over rows 16g+15 .. 16g (L2-hot), proc group NG-1-g
    float x[16], nx[16];
    ld16(dd+(RR*g+RR-1)*W+c0,x);          // serial row (from serial_fwd)
    ld16(dd+(RR*g+RR-2)*W+c0,nx);
    for (int k=1;k<RR;k++) {
        age_step(x,t);
        #pragma unroll
        for (int c=0;c<16;c++) x[c]=fminf(x[c],nx[c]);
        if (k<RR-1) ld16(dd+(RR*g+RR-2-k)*W+c0,nx);
    }
    st16(g_L+(img*NG+(NG-1-g))*W+c0,x);
}

__global__ __launch_bounds__(32) void serial_bwd_kernel() {
    const int img=blockIdx.x, t=threadIdx.x, c0=t*16;
    const unsigned FM=0xffffffffu;
    float* dd=g_dist+img*NPIX;
    const float* Lb=g_L+img*NG*W;
    float ar[16];
    #pragma unroll
    for (int c=0;c<16;c++) ar[c]=CA*(float)(W-1-(c0+c));
    float p[16];
    #pragma unroll
    for (int c=0;c<16;c++) p[c]=CINF;
    float lmax=0.0f;
    float Lc[16]; ld16(Lb+c0,Lc);
    for (int g=0;g<NG;g++) {
        float Ln[16];
        if (g<NG-1) ld16(Lb+(g+1)*W+c0,Ln);
        composed_step16(p,Lc,ar,t,1);
        #pragma unroll
        for (int c=0;c<16;c++) lmax=fmaxf(lmax,p[c]);
        st16(dd+(511-(RR*g+RR-1))*W+c0,p);
        #pragma unroll
        for (int c=0;c<16;c++) Lc[c]=Ln[c];
    }
    #pragma unroll
    for (int d=16;d>0;d>>=1) lmax=fmaxf(lmax,__shfl_xor_sync(FM,lmax,d));
    if (t==0) atomicMax(&g_mxi[img],__float_as_int(lmax));
}

__global__ __launch_bounds__(32) void fill_bwd_kernel() {
    const int g=blockIdx.x, img=blockIdx.y, t=threadIdx.x, c0=t*16;
    const unsigned FM=0xffffffffu;
    float* dd=g_dist+img*NPIX;
    float ar[16];
    #pragma unroll
    for (int c=0;c<16;c++) ar[c]=CA*(float)(W-1-(c0+c));
    float p[16];
    if (g==0) {
        #pragma unroll
        for (int c=0;c<16;c++) p[c]=CINF;
    } else ld16(dd+(512-RR*g)*W+c0,p);
    float lmax=0.0f;
    float drw[16], nxt[16];
    ld16(dd+(511-RR*g)*W+c0,drw);
    ld16(dd+(511-(RR*g+1))*W+c0,nxt);
    for (int k=0;k<RR-1;k++) {
        row_step_bwd(p,drw,ar,t);
        #pragma unroll
        for (int c=0;c<16;c++) { lmax=fmaxf(lmax,p[c]); drw[c]=nxt[c]; }
        st16(dd+(511-(RR*g+k))*W+c0,p);
        if (k<RR-2) ld16(dd+(511-(RR*g+k+2))*W+c0,nxt);
    }
    #pragma unroll
    for (int d=16;d>0;d>>=1) lmax=fmaxf(lmax,__shfl_xor_sync(FM,lmax,d));
    if (t==0) atomicMax(&g_mxi[img],__float_as_int(lmax));
}

__global__ __launch_bounds__(LBLK) void loss_partial(const float* __restrict__ pred,
                                                     const int* __restrict__ target) {
    const int img=blockIdx.x/BPI, sub=blockIdx.x%BPI, base=img*NPIX;
    const float mx=__int_as_float(g_mxi[img]);
    const int hfg=g_flags[img]&1;
    const float inv=1.0f/fmaxf(mx,1e-12f);
    const int usediv=(mx>0.0f)?1:0;
    float sF=0.f,sB=0.f,sP=0.f,sT=0.f,sPT=0.f;
    for (int idx=sub*LBLK+threadIdx.x; idx<NPIX; idx+=BPI*LBLK) {
        float x=pred[base+idx];
        int tv=target[base+idx];
        float d=g_dist[base+idx];
        float p=1.0f/(1.0f+expf(-x));
        float ax=fabsf(x);
        float bce=log1pf(expf(-ax))+(tv?fmaxf(-x,0.0f):fmaxf(x,0.0f));
        float pt=tv?p:(1.0f-p);
        float omp=1.0f-pt;
        float alpha=tv?0.25f:0.75f;
        sF+=alpha*omp*omp*bce;
        float dn=hfg?(usediv?d*inv:d):1.0f;
        sB+=omp*(1.0f+dn);
        sP+=p;
        if (tv) { sT+=1.0f; sPT+=p; }
    }
    float vals[5]={sF,sB,sP,sT,sPT};
    #pragma unroll
    for (int k=0;k<5;k++) {
        float v=vals[k];
        #pragma unroll
        for (int d=16;d>0;d>>=1) v+=__shfl_xor_sync(0xffffffffu,v,d);
        vals[k]=v;
    }
    __shared__ float s5[LBLK/32][5];
    int lane=threadIdx.x&31, wid=threadIdx.x>>5;
    if (lane==0) {
        #pragma unroll
        for (int k=0;k<5;k++) s5[wid][k]=vals[k];
    }
    __syncthreads();
    if (threadIdx.x==0) {
        #pragma unroll
        for (int k=0;k<5;k++) {
            float a=0.f;
            for (int w=0;w<LBLK/32;w++) a+=s5[w][k];
            g_part[blockIdx.x*5+k]=a;
        }
    }
}

__global__ __launch_bounds__(512) void loss_final(const float* __restrict__ lv,
                                                  float* __restrict__ out, int out_size) {
    __shared__ double sd[BATCH][4];
    const unsigned FM=0xffffffffu;
    int t=threadIdx.x;                 // 512 = 16 images x 32 blocks
    int img=t>>5, b=t&31;
    const float* pp=g_part+(img*BPI+b)*5;
    double F=pp[0], Bd=pp[1], P=pp[2], T=pp[3], PT=pp[4];
    #pragma unroll
    for (int d=16;d>0;d>>=1) {
        F+=__shfl_xor_sync(FM,F,d);
        Bd+=__shfl_xor_sync(FM,Bd,d);
        P+=__shfl_xor_sync(FM,P,d);
        T+=__shfl_xor_sync(FM,T,d);
        PT+=__shfl_xor_sync(FM,PT,d);
    }
    if (b==0) {
        double total=P+T, uni=total-PT;
        sd[img][0]=F; sd[img][1]=Bd;
        sd[img][2]=(2.0*PT+1e-6)/(total+1e-6);
        sd[img][3]=(PT+1e-6)/(uni+1e-6);
    }
    __syncthreads();
    if (t==0) {
        double Fa=0,Bda=0,D=0,I=0;
        for (int k=0;k<BATCH;k++) { Fa+=sd[k][0]; Bda+=sd[k][1]; D+=sd[k][2]; I+=sd[k][3]; }
        double N=(double)BATCH*(double)NPIX;
        double focal=Fa/N, bnd=Bda/N;
        double dice=1.0-D/(double)BATCH, iou=1.0-I/(double)BATCH;
        double l0=lv[0],l1=lv[1],l2=lv[2],l3=lv[3];
        double tot=exp(-l0)*focal+l0+exp(-l1)*dice+l1+exp(-l2)*bnd+l2+exp(-l3)*iou+l3;
        if (out_size>0) out[0]=(float)tot;
        if (out_size>1) out[1]=(float)focal;
        if (out_size>2) out[2]=(float)dice;
        if (out_size>3) out[3]=(float)bnd;
        if (out_size>4) out[4]=(float)iou;
    }
}

extern "C" void kernel_launch(void* const* d_in, const int* in_sizes, int n_in,
                              void* d_out, int out_size) {
    const float* pred   = (const float*)d_in[0];
    const int*   target = (const int*)d_in[1];
    const float* lv     = (const float*)d_in[2];
    float* out = (float*)d_out;

    dim3 gg(NG, BATCH);
    seed_kernel<<<BATCH, 128>>>(target);
    Lfwd_kernel<<<gg, 32>>>();
    serial_fwd_kernel<<<BATCH, 32>>>();
    fillfwd_lbwd_kernel<<<gg, 32>>>();
    serial_bwd_kernel<<<BATCH, 32>>>();
    fill_bwd_kernel<<<gg, 32>>>();
    loss_partial<<<NLB, LBLK>>>(pred, target);
    loss_final<<<1, 512>>>(lv, out, out_size);
}

// round 16
// speedup vs baseline: 1.4819x; 1.4819x over previous
#include <cuda_runtime.h>
#include <math.h>

#define H 512
#define W 512
#define BATCH 16
#define NPIX (H*W)
#define CA 0.955f
#define CB 1.3693f
#define CINF 1e6f
#define BIG 1e30f
#define NG 32                 // 32 groups of 16 rows
#define RR 16
#define LBLK 256
#define BPI 32
#define NLB (BATCH*BPI)

#define SD  ((float)((double)CB-(double)CA))        // slope
#define S16 ((float)(16.0*((double)CB-(double)CA))) // 16*s
#define C16A ((float)(16.0*(double)CA))

__device__ float    g_dist[BATCH*NPIX];
__device__ int      g_mxi[BATCH];
__device__ int      g_flags[BATCH];
__device__ float    g_part[NLB*5];
__device__ unsigned g_seed[BATCH*H*16];
__device__ float    g_L[BATCH*NG*W];

__device__ __forceinline__ void ld16(const float* b, float* a) {
    float4 x0=*(const float4*)(b+0), x1=*(const float4*)(b+4);
    float4 x2=*(const float4*)(b+8), x3=*(const float4*)(b+12);
    a[0]=x0.x;a[1]=x0.y;a[2]=x0.z;a[3]=x0.w; a[4]=x1.x;a[5]=x1.y;a[6]=x1.z;a[7]=x1.w;
    a[8]=x2.x;a[9]=x2.y;a[10]=x2.z;a[11]=x2.w; a[12]=x3.x;a[13]=x3.y;a[14]=x3.z;a[15]=x3.w;
}
__device__ __forceinline__ void st16(float* b, const float* a) {
    *(float4*)(b+0)=make_float4(a[0],a[1],a[2],a[3]);
    *(float4*)(b+4)=make_float4(a[4],a[5],a[6],a[7]);
    *(float4*)(b+8)=make_float4(a[8],a[9],a[10],a[11]);
    *(float4*)(b+12)=make_float4(a[12],a[13],a[14],a[15]);
}
__device__ __forceinline__ float scan_up(float x, int t) {
    const unsigned FM=0xffffffffu; float o;
    o=__shfl_up_sync(FM,x,1);  if(t>=1)  x=fminf(x,o);
    o=__shfl_up_sync(FM,x,2);  if(t>=2)  x=fminf(x,o);
    o=__shfl_up_sync(FM,x,4);  if(t>=4)  x=fminf(x,o);
    o=__shfl_up_sync(FM,x,8);  if(t>=8)  x=fminf(x,o);
    o=__shfl_up_sync(FM,x,16); if(t>=16) x=fminf(x,o);
    return x;
}
__device__ __forceinline__ float scan_dn(float x, int t) {
    const unsigned FM=0xffffffffu; float o;
    o=__shfl_down_sync(FM,x,1);  if(t<=30) x=fminf(x,o);
    o=__shfl_down_sync(FM,x,2);  if(t<=29) x=fminf(x,o);
    o=__shfl_down_sync(FM,x,4);  if(t<=27) x=fminf(x,o);
    o=__shfl_down_sync(FM,x,8);  if(t<=23) x=fminf(x,o);
    o=__shfl_down_sync(FM,x,16); if(t<=15) x=fminf(x,o);
    return x;
}
__device__ __forceinline__ unsigned seed_bits(int img, int r, int t) {
    return (g_seed[img*H*16 + r*16 + (t>>1)] >> ((t&1)*16)) & 0xffffu;
}
__device__ __forceinline__ void row_step_fwd(float* p, unsigned hw, const float* aj, int t) {
    const unsigned FM=0xffffffffu;
    float pvL=__shfl_up_sync(FM,p[15],1);  if(t==0)  pvL=CINF;
    float pvR=__shfl_down_sync(FM,p[0],1); if(t==31) pvR=CINF;
    float v[16];
    #pragma unroll
    for (int c=0;c<16;c++) {
        float pl=(c==0)?pvL:p[c-1], pr=(c==15)?pvR:p[c+1];
        float dv=((hw>>c)&1u)?0.0f:CINF;
        v[c]=fminf(fminf(dv,p[c]+CA),fminf(pl,pr)+CB)-aj[c];
    }
    #pragma unroll
    for (int c=1;c<16;c++) v[c]=fminf(v[c-1],v[c]);
    float s=scan_up(v[15],t);
    float excl=__shfl_up_sync(FM,s,1); if(t==0) excl=BIG;
    #pragma unroll
    for (int c=0;c<16;c++) p[c]=aj[c]+fminf(excl,v[c]);
}
__device__ __forceinline__ void row_step_bwd(float* p, const float* drw, const float* ar, int t) {
    const unsigned FM=0xffffffffu;
    float pvL=__shfl_up_sync(FM,p[15],1);  if(t==0)  pvL=CINF;
    float pvR=__shfl_down_sync(FM,p[0],1); if(t==31) pvR=CINF;
    float v[16];
    #pragma unroll
    for (int c=0;c<16;c++) {
        float pl=(c==0)?pvL:p[c-1], pr=(c==15)?pvR:p[c+1];
        v[c]=fminf(fminf(drw[c],p[c]+CA),fminf(pl,pr)+CB)-ar[c];
    }
    #pragma unroll
    for (int c=14;c>=0;c--) v[c]=fminf(v[c],v[c+1]);
    float s=scan_dn(v[0],t);
    float excl=__shfl_down_sync(FM,s,1); if(t==31) excl=BIG;
    #pragma unroll
    for (int c=0;c<16;c++) p[c]=ar[c]+fminf(excl,v[c]);
}
__device__ __forceinline__ void age_step(float* x, int t) {
    const unsigned FM=0xffffffffu;
    float xl=__shfl_up_sync(FM,x[15],1);  if(t==0)  xl=CINF;
    float xr=__shfl_down_sync(FM,x[0],1); if(t==31) xr=CINF;
    float y[16];
    #pragma unroll
    for (int c=0;c<16;c++) {
        float l=(c==0)?xl:x[c-1], r=(c==15)?xr:x[c+1];
        y[c]=fminf(x[c]+CA,fminf(l,r)+CB);
    }
    #pragma unroll
    for (int c=0;c<16;c++) x[c]=y[c];
}
// composed 16-row step: band via slope doubling, then cummin. dir 0=fwd,1=bwd
__device__ __forceinline__ void composed_step16(float* p, const float* Lc,
                                                const float* ax, int t, int dir) {
    const unsigned FM=0xffffffffu;
    float pe[48];           // cols c0-16 .. c0+31
    #pragma unroll
    for (int k=0;k<16;k++) { float h=__shfl_up_sync(FM,p[k],1); pe[k]=(t==0)?CINF:h; }
    #pragma unroll
    for (int c=0;c<16;c++) pe[16+c]=p[c];
    #pragma unroll
    for (int k=0;k<16;k++) { float h=__shfl_down_sync(FM,p[k],1); pe[32+k]=(t==31)?CINF:h; }
    float TL[16], TR[16];
    #pragma unroll
    for (int c=0;c<16;c++) { TL[c]=pe[c]+S16; TR[c]=pe[32+c]+S16; }
    float A[48];
    #pragma unroll
    for (int i=0;i<48;i++) A[i]=pe[i];
    #pragma unroll
    for (int i=31;i>=2;i--)  A[i]=fminf(A[i],A[i-1]+SD);
    #pragma unroll
    for (int i=31;i>=4;i--)  A[i]=fminf(A[i],A[i-2]+(2.0f*SD));
    #pragma unroll
    for (int i=31;i>=8;i--)  A[i]=fminf(A[i],A[i-4]+(4.0f*SD));
    #pragma unroll
    for (int i=31;i>=16;i--) A[i]=fminf(A[i],A[i-8]+(8.0f*SD));
    #pragma unroll
    for (int i=16;i<=45;i++) pe[i]=fminf(pe[i],pe[i+1]+SD);
    #pragma unroll
    for (int i=16;i<=43;i++) pe[i]=fminf(pe[i],pe[i+2]+(2.0f*SD));
    #pragma unroll
    for (int i=16;i<=39;i++) pe[i]=fminf(pe[i],pe[i+4]+(4.0f*SD));
    #pragma unroll
    for (int i=16;i<=31;i++) pe[i]=fminf(pe[i],pe[i+8]+(8.0f*SD));
    float v[16];
    #pragma unroll
    for (int c=0;c<16;c++) {
        float b=fminf(fminf(A[16+c],TL[c]),fminf(pe[16+c],TR[c]));
        v[c]=fminf(Lc[c],b+C16A)-ax[c];
    }
    if (dir==0) {
        #pragma unroll
        for (int c=1;c<16;c++) v[c]=fminf(v[c-1],v[c]);
        float s=scan_up(v[15],t);
        float excl=__shfl_up_sync(FM,s,1); if(t==0) excl=BIG;
        #pragma unroll
        for (int c=0;c<16;c++) p[c]=ax[c]+fminf(excl,v[c]);
    } else {
        #pragma unroll
        for (int c=14;c>=0;c--) v[c]=fminf(v[c],v[c+1]);
        float s=scan_dn(v[0],t);
        float excl=__shfl_down_sync(FM,s,1); if(t==31) excl=BIG;
        #pragma unroll
        for (int c=0;c<16;c++) p[c]=ax[c]+fminf(excl,v[c]);
    }
}

__global__ __launch_bounds__(128) void seed_kernel(const int* __restrict__ target) {
    __shared__ unsigned mbits[H*18];
    __shared__ int sflag[2];
    const int img=blockIdx.x;
    const int* tg=target+img*NPIX;
    unsigned* sb=g_seed+img*H*16;
    const int tid=threadIdx.x, lane=tid&31, sl=tid&7, sg=tid>>3, col0=tid*4;
    const unsigned FM=0xffffffffu;
    if (tid<2) sflag[tid]=0;
    if (tid==0) g_mxi[img]=0;
    for (int r=tid;r<H;r+=128) { mbits[r*18+0]=0u; mbits[r*18+17]=0u; }
    __syncthreads();
    bool any1=false, any0=false;
    for (int r=0;r<H;r++) {
        int4 tv=*(const int4*)(tg+r*W+col0);
        unsigned nib=(unsigned)(tv.x!=0)|((unsigned)(tv.y!=0)<<1)
                    |((unsigned)(tv.z!=0)<<2)|((unsigned)(tv.w!=0)<<3);
        any1|=(nib!=0u); any0|=(nib!=15u);
        unsigned word=nib<<(4*sl);
        word|=__shfl_xor_sync(FM,word,1);
        word|=__shfl_xor_sync(FM,word,2);
        word|=__shfl_xor_sync(FM,word,4);
        if (sl==0) mbits[r*18+1+sg]=word;
    }
    if (__any_sync(FM,any1)&&lane==0) atomicOr(&sflag[0],1);
    if (__any_sync(FM,any0)&&lane==0) atomicOr(&sflag[1],1);
    __syncthreads();
    const int hasb=sflag[0]&sflag[1];
    for (int idx=tid;idx<H*16;idx+=128) {
        int r=idx>>4, w=idx&15;
        unsigned swd;
        if (hasb) {
            unsigned dil=0u, ero=0xffffffffu;
            #pragma unroll
            for (int dr=-1;dr<=1;dr++) {
                int r2=r+dr;
                if (r2<0||r2>=H) continue;
                unsigned M=mbits[r2*18+1+w], Ml=mbits[r2*18+w], Mr=mbits[r2*18+2+w];
                unsigned Mlg=(w==0)?0xffffffffu:Ml, Mrg=(w==15)?0xffffffffu:Mr;
                dil|=M|__funnelshift_l(Ml,M,1)|__funnelshift_r(M,Mr,1);
                ero&=M&__funnelshift_l(Mlg,M,1)&__funnelshift_r(M,Mrg,1);
            }
            swd=dil&~ero;
        } else swd=~mbits[r*18+1+w];
        sb[idx]=swd;
    }
    if (tid==0) g_flags[img]=sflag[0]|(sflag[1]<<1);
}

__global__ __launch_bounds__(32) void Lfwd_kernel() {
    const int g=blockIdx.x, img=blockIdx.y, t=threadIdx.x, c0=t*16;
    float x[16];
    unsigned hw=seed_bits(img,RR*g,t);
    #pragma unroll
    for (int c=0;c<16;c++) x[c]=((hw>>c)&1u)?0.0f:CINF;
    for (int k=1;k<RR;k++) {
        age_step(x,t);
        unsigned h2=seed_bits(img,RR*g+k,t);
        #pragma unroll
        for (int c=0;c<16;c++) x[c]=fminf(x[c],((h2>>c)&1u)?0.0f:CINF);
    }
    st16(g_L+(img*NG+g)*W+c0,x);
}

__global__ __launch_bounds__(32) void Lbwd_kernel() {
    const int g=blockIdx.x, img=blockIdx.y, t=threadIdx.x, c0=t*16;
    const float* dd=g_dist+img*NPIX;
    float x[16], s2[16];
    ld16(dd+(511-RR*g)*W+c0,x);
    for (int k=1;k<RR;k++) {
        age_step(x,t);
        ld16(dd+(511-(RR*g+k))*W+c0,s2);
        #pragma unroll
        for (int c=0;c<16;c++) x[c]=fminf(x[c],s2[c]);
    }
    st16(g_L+(img*NG+g)*W+c0,x);
}

__global__ __launch_bounds__(32) void serial_fwd_kernel() {
    const int img=blockIdx.x, t=threadIdx.x, c0=t*16;
    float* dd=g_dist+img*NPIX;
    const float* Lb=g_L+img*NG*W;
    float aj[16];
    #pragma unroll
    for (int c=0;c<16;c++) aj[c]=CA*(float)(c0+c);
    float p[16];
    #pragma unroll
    for (int c=0;c<16;c++) p[c]=CINF;
    float Lc[16]; ld16(Lb+c0,Lc);
    for (int g=0;g<NG;g++) {
        float Ln[16];
        if (g<NG-1) ld16(Lb+(g+1)*W+c0,Ln);
        composed_step16(p,Lc,aj,t,0);
        st16(dd+(RR*g+RR-1)*W+c0,p);
        #pragma unroll
        for (int c=0;c<16;c++) Lc[c]=Ln[c];
    }
}

__global__ __launch_bounds__(32) void fill_fwd_kernel() {
    const int g=blockIdx.x, img=blockIdx.y, t=threadIdx.x, c0=t*16;
    float* dd=g_dist+img*NPIX;
    float aj[16];
    #pragma unroll
    for (int c=0;c<16;c++) aj[c]=CA*(float)(c0+c);
    float p[16];
    if (g==0) {
        #pragma unroll
        for (int c=0;c<16;c++) p[c]=CINF;
    } else ld16(dd+(RR*g-1)*W+c0,p);
    for (int k=0;k<RR-1;k++) {
        row_step_fwd(p,seed_bits(img,RR*g+k,t),aj,t);
        st16(dd+(RR*g+k)*W+c0,p);
    }
}

__global__ __launch_bounds__(32) void serial_bwd_kernel() {
    const int img=blockIdx.x, t=threadIdx.x, c0=t*16;
    const unsigned FM=0xffffffffu;
    float* dd=g_dist+img*NPIX;
    const float* Lb=g_L+img*NG*W;
    float ar[16];
    #pragma unroll
    for (int c=0;c<16;c++) ar[c]=CA*(float)(W-1-(c0+c));
    float p[16];
    #pragma unroll
    for (int c=0;c<16;c++) p[c]=CINF;
    float lmax=0.0f;
    float Lc[16]; ld16(Lb+c0,Lc);
    for (int g=0;g<NG;g++) {
        float Ln[16];
        if (g<NG-1) ld16(Lb+(g+1)*W+c0,Ln);
        composed_step16(p,Lc,ar,t,1);
        #pragma unroll
        for (int c=0;c<16;c++) lmax=fmaxf(lmax,p[c]);
        st16(dd+(511-(RR*g+RR-1))*W+c0,p);
        #pragma unroll
        for (int c=0;c<16;c++) Lc[c]=Ln[c];
    }
    #pragma unroll
    for (int d=16;d>0;d>>=1) lmax=fmaxf(lmax,__shfl_xor_sync(FM,lmax,d));
    if (t==0) atomicMax(&g_mxi[img],__float_as_int(lmax));
}

__global__ __launch_bounds__(32) void fill_bwd_kernel() {
    const int g=blockIdx.x, img=blockIdx.y, t=threadIdx.x, c0=t*16;
    const unsigned FM=0xffffffffu;
    float* dd=g_dist+img*NPIX;
    float ar[16];
    #pragma unroll
    for (int c=0;c<16;c++) ar[c]=CA*(float)(W-1-(c0+c));
    float p[16];
    if (g==0) {
        #pragma unroll
        for (int c=0;c<16;c++) p[c]=CINF;
    } else ld16(dd+(512-RR*g)*W+c0,p);   // serial output at proc row RR*g-1
    float lmax=0.0f;
    for (int k=0;k<RR-1;k++) {
        float drw[16];
        ld16(dd+(511-(RR*g+k))*W+c0,drw);
        row_step_bwd(p,drw,ar,t);
        #pragma unroll
        for (int c=0;c<16;c++) lmax=fmaxf(lmax,p[c]);
        st16(dd+(511-(RR*g+k))*W+c0,p);
    }
    #pragma unroll
    for (int d=16;d>0;d>>=1) lmax=fmaxf(lmax,__shfl_xor_sync(FM,lmax,d));
    if (t==0) atomicMax(&g_mxi[img],__float_as_int(lmax));
}

__global__ __launch_bounds__(LBLK) void loss_partial(const float* __restrict__ pred,
                                                     const int* __restrict__ target) {
    const int img=blockIdx.x/BPI, sub=blockIdx.x%BPI, base=img*NPIX;
    const float mx=__int_as_float(g_mxi[img]);
    const int hfg=g_flags[img]&1;
    const float inv=1.0f/fmaxf(mx,1e-12f);
    const int usediv=(mx>0.0f)?1:0;
    float sF=0.f,sB=0.f,sP=0.f,sT=0.f,sPT=0.f;
    for (int idx=sub*LBLK+threadIdx.x; idx<NPIX; idx+=BPI*LBLK) {
        float x=pred[base+idx];
        int tv=target[base+idx];
        float d=g_dist[base+idx];
        float p=1.0f/(1.0f+expf(-x));
        float ax=fabsf(x);
        float bce=log1pf(expf(-ax))+(tv?fmaxf(-x,0.0f):fmaxf(x,0.0f));
        float pt=tv?p:(1.0f-p);
        float omp=1.0f-pt;
        float alpha=tv?0.25f:0.75f;
        sF+=alpha*omp*omp*bce;
        float dn=hfg?(usediv?d*inv:d):1.0f;
        sB+=omp*(1.0f+dn);
        sP+=p;
        if (tv) { sT+=1.0f; sPT+=p; }
    }
    float vals[5]={sF,sB,sP,sT,sPT};
    #pragma unroll
    for (int k=0;k<5;k++) {
        float v=vals[k];
        #pragma unroll
        for (int d=16;d>0;d>>=1) v+=__shfl_xor_sync(0xffffffffu,v,d);
        vals[k]=v;
    }
    __shared__ float s5[LBLK/32][5];
    int lane=threadIdx.x&31, wid=threadIdx.x>>5;
    if (lane==0) {
        #pragma unroll
        for (int k=0;k<5;k++) s5[wid][k]=vals[k];
    }
    __syncthreads();
    if (threadIdx.x==0) {
        #pragma unroll
        for (int k=0;k<5;k++) {
            float a=0.f;
            for (int w=0;w<LBLK/32;w++) a+=s5[w][k];
            g_part[blockIdx.x*5+k]=a;
        }
    }
}

__global__ __launch_bounds__(512) void loss_final(const float* __restrict__ lv,
                                                  float* __restrict__ out, int out_size) {
    __shared__ double sd[BATCH][4];
    const unsigned FM=0xffffffffu;
    int t=threadIdx.x;                 // 512 = 16 images x 32 blocks
    int img=t>>5, b=t&31;
    const float* pp=g_part+(img*BPI+b)*5;
    double F=pp[0], Bd=pp[1], P=pp[2], T=pp[3], PT=pp[4];
    #pragma unroll
    for (int d=16;d>0;d>>=1) {
        F+=__shfl_xor_sync(FM,F,d);
        Bd+=__shfl_xor_sync(FM,Bd,d);
        P+=__shfl_xor_sync(FM,P,d);
        T+=__shfl_xor_sync(FM,T,d);
        PT+=__shfl_xor_sync(FM,PT,d);
    }
    if (b==0) {
        double total=P+T, uni=total-PT;
        sd[img][0]=F; sd[img][1]=Bd;
        sd[img][2]=(2.0*PT+1e-6)/(total+1e-6);
        sd[img][3]=(PT+1e-6)/(uni+1e-6);
    }
    __syncthreads();
    if (t==0) {
        double Fa=0,Bda=0,D=0,I=0;
        for (int k=0;k<BATCH;k++) { Fa+=sd[k][0]; Bda+=sd[k][1]; D+=sd[k][2]; I+=sd[k][3]; }
        double N=(double)BATCH*(double)NPIX;
        double focal=Fa/N, bnd=Bda/N;
        double dice=1.0-D/(double)BATCH, iou=1.0-I/(double)BATCH;
        double l0=lv[0],l1=lv[1],l2=lv[2],l3=lv[3];
        double tot=exp(-l0)*focal+l0+exp(-l1)*dice+l1+exp(-l2)*bnd+l2+exp(-l3)*iou+l3;
        if (out_size>0) out[0]=(float)tot;
        if (out_size>1) out[1]=(float)focal;
        if (out_size>2) out[2]=(float)dice;
        if (out_size>3) out[3]=(float)bnd;
        if (out_size>4) out[4]=(float)iou;
    }
}

extern "C" void kernel_launch(void* const* d_in, const int* in_sizes, int n_in,
                              void* d_out, int out_size) {
    const float* pred   = (const float*)d_in[0];
    const int*   target = (const int*)d_in[1];
    const float* lv     = (const float*)d_in[2];
    float* out = (float*)d_out;

    dim3 gg(NG, BATCH);
    seed_kernel<<<BATCH, 128>>>(target);
    Lfwd_kernel<<<gg, 32>>>();
    serial_fwd_kernel<<<BATCH, 32>>>();
    fill_fwd_kernel<<<gg, 32>>>();
    Lbwd_kernel<<<gg, 32>>>();
    serial_bwd_kernel<<<BATCH, 32>>>();
    fill_bwd_kernel<<<gg, 32>>>();
    loss_partial<<<NLB, LBLK>>>(pred, target);
    loss_final<<<1, 512>>>(lv, out, out_size);
}